// round 13
// baseline (speedup 1.0000x reference)
#include <cuda_runtime.h>
#include <cuda_bf16.h>
#include <mma.h>
#include <math.h>
#include <cstdint>

using namespace nvcuda;

// Problem constants
#define PB 256      // batch
#define PL 64       // leaves
#define PD 1024     // dim
#define PC 500      // classes
#define PN 127      // nodes = 2L-1
#define PS 63       // steps = L-1
#define HB 512      // half-spectrum bins stored per node

// Scratch
static __device__ __nv_bfloat16 g_tdb[(size_t)PB * PN * PD];  // 66 MB (GEMM A)
static __device__ float2        g_fd[(size_t)PB * PN * HB];   // 133 MB (half spectra)
static __device__ __nv_bfloat16 g_wb[(size_t)PC * PD];        // 1 MB  (W in bf16)
static __device__ float2        g_w1024[512];                 // W1024^k (untangle)
static __device__ float2        g_w512[512];                  // W512^j  (FFT twiddles)

// ---------------------------------------------------------------------------
// Setup: twiddle tables + W bf16 conversion.
__global__ void setup_kernel(const float* __restrict__ W) {
    int g = blockIdx.x;
    if (g == 0) {
        for (int i = threadIdx.x; i < 512; i += 256) {
            float sn, cs;
            sincosf(-6.283185307179586f * (float)i / 1024.f, &sn, &cs);
            g_w1024[i] = make_float2(cs, sn);
        }
    } else if (g == 1) {
        for (int i = threadIdx.x; i < 512; i += 256) {
            float sn, cs;
            sincosf(-6.283185307179586f * (float)i / 512.f, &sn, &cs);
            g_w512[i] = make_float2(cs, sn);
        }
    } else {
        int i = (g - 2) * 1024 + threadIdx.x * 4;
        float4 v = *(const float4*)(W + i);
        __nv_bfloat16* o = g_wb + i;
        o[0] = __float2bfloat16(v.x);
        o[1] = __float2bfloat16(v.y);
        o[2] = __float2bfloat16(v.z);
        o[3] = __float2bfloat16(v.w);
    }
}

// ---------------------------------------------------------------------------
// Complex helpers
__device__ __forceinline__ float2 cadd(float2 a, float2 b) { return make_float2(a.x + b.x, a.y + b.y); }
__device__ __forceinline__ float2 csub(float2 a, float2 b) { return make_float2(a.x - b.x, a.y - b.y); }
__device__ __forceinline__ float2 cmul(float2 a, float2 b) {
    return make_float2(fmaf(a.x, b.x, -a.y * b.y), fmaf(a.x, b.y, a.y * b.x));
}
template<bool INV>
__device__ __forceinline__ float2 crot(float2 a) {   // * (-i) fwd, * (+i) inv
    return INV ? make_float2(-a.y, a.x) : make_float2(a.y, -a.x);
}

// In-register 8-point DFT, natural-order in/out.
template<bool INV>
__device__ __forceinline__ void fft8(float2* a) {
    const float r = 0.70710678118654752440f;
    const float2 w1 = INV ? make_float2(r, r)  : make_float2(r, -r);
    const float2 w3 = INV ? make_float2(-r, r) : make_float2(-r, -r);
    float2 b0 = cadd(a[0], a[4]), b4 = csub(a[0], a[4]);
    float2 b1 = cadd(a[1], a[5]), b5 = cmul(csub(a[1], a[5]), w1);
    float2 b2 = cadd(a[2], a[6]), b6 = crot<INV>(csub(a[2], a[6]));
    float2 b3 = cadd(a[3], a[7]), b7 = cmul(csub(a[3], a[7]), w3);
    float2 c0 = cadd(b0, b2), c2 = csub(b0, b2);
    float2 c1 = cadd(b1, b3), c3 = crot<INV>(csub(b1, b3));
    float2 c4 = cadd(b4, b6), c6 = csub(b4, b6);
    float2 c5 = cadd(b5, b7), c7 = crot<INV>(csub(b5, b7));
    a[0] = cadd(c0, c1); a[4] = csub(c0, c1);
    a[2] = cadd(c2, c3); a[6] = csub(c2, c3);
    a[1] = cadd(c4, c5); a[5] = csub(c4, c5);
    a[3] = cadd(c6, c7); a[7] = csub(c6, c7);
}

// Padded natural-order index: p(n) = n + n/8 (row stride 9, max 574 < 576).
#define SBP(s, n) ((s)[(n) + ((n) >> 3)])

// 512-pt complex FFT, radix-8^3, 64 threads per FFT, 8 values in registers.
// Block-wide syncs: ALL threads in the block must call this together.
template<bool INV>
__device__ __forceinline__ void fft512_reg(float2* a, float2* sb, int t) {
    fft8<INV>(a);
    sb[t] = a[0];
#pragma unroll
    for (int k1 = 1; k1 < 8; k1++) {
        float2 w = g_w512[t * k1];
        if (INV) w.y = -w.y;
        sb[72 * k1 + t] = cmul(a[k1], w);
    }
    __syncthreads();
    const int k1 = t >> 3, m2 = t & 7;
    {
        const float2* base = sb + 72 * k1 + m2;
#pragma unroll
        for (int m1 = 0; m1 < 8; m1++) a[m1] = base[8 * m1];
    }
    __syncthreads();
    fft8<INV>(a);
    sb[72 * k1 + m2] = a[0];
#pragma unroll
    for (int j1 = 1; j1 < 8; j1++) {
        float2 w = g_w512[8 * m2 * j1];
        if (INV) w.y = -w.y;
        sb[72 * k1 + 9 * j1 + m2] = cmul(a[j1], w);
    }
    __syncthreads();
    const int j1 = t & 7;
    {
        const float2* base = sb + 72 * k1 + 9 * j1;
#pragma unroll
        for (int m = 0; m < 8; m++) a[m] = base[m];
    }
    __syncthreads();
    fft8<INV>(a);
#pragma unroll
    for (int j2 = 0; j2 < 8; j2++) {
        int n = k1 + 8 * j1 + 64 * j2;
        SBP(sb, n) = a[j2];
    }
    __syncthreads();
}

// Reconstruct Z[k] (k = t + 64q) of the inverse packed-real FFT input from a
// half spectrum fd[0..511] (bin 0 = (X0, X512)).
__device__ __forceinline__ void irfft_load(const float2* __restrict__ fd,
                                           float2* a, int t) {
#pragma unroll
    for (int q = 0; q < 8; q++) {
        int k = t + 64 * q;
        float2 z;
        if (k == 0) {
            float2 p = fd[0];
            z = make_float2(0.5f * (p.x + p.y), 0.5f * (p.x - p.y));
        } else if (k == 256) {
            float2 x = fd[256];
            z = make_float2(x.x, -x.y);
        } else if (k < 256) {
            float2 Xk = fd[k], Xk2 = fd[512 - k];
            float ex = 0.5f * (Xk.x + Xk2.x), ey = 0.5f * (Xk.y - Xk2.y);
            float dx = Xk.x - Xk2.x, dy = Xk.y + Xk2.y;
            float2 w = g_w1024[k];
            float ox = 0.5f * (dx * w.x + dy * w.y);
            float oy = 0.5f * (dy * w.x - dx * w.y);
            z = make_float2(ex - oy, ey + ox);
        } else {
            int kk = 512 - k;
            float2 Xk = fd[kk], Xk2 = fd[k];
            float ex = 0.5f * (Xk.x + Xk2.x), ey = 0.5f * (Xk.y - Xk2.y);
            float dx = Xk.x - Xk2.x, dy = Xk.y + Xk2.y;
            float2 w = g_w1024[kk];
            float ox = 0.5f * (dx * w.x + dy * w.y);
            float oy = 0.5f * (dy * w.x - dx * w.y);
            z = make_float2(ex + oy, ox - ey);
        }
        a[q] = z;
    }
}

// Coalesced bf16 writeout of an iFFT result held in padded scratch.
__device__ __forceinline__ void irfft_store(const float2* s, __nv_bfloat16* td, int t) {
    const float sc = 1.f / 512.f;
    int4* td4 = (int4*)td;
#pragma unroll
    for (int h = 0; h < 2; h++) {
        union { int4 v; __nv_bfloat162 e[4]; } u;
#pragma unroll
        for (int e2 = 0; e2 < 4; e2++) {
            float2 z = s[9 * t + h * 4 + e2];        // p(8t+e) = 9t+e
            u.e[e2] = __floats2bfloat162_rn(z.x * sc, z.y * sc);
        }
        td4[2 * t + h] = u.v;
    }
}

// ---------------------------------------------------------------------------
// Kernel 1: leaf gather + mask + L2-normalize -> bf16 TD; rfft -> half FD.
__global__ __launch_bounds__(256) void leaf_kernel(const int* __restrict__ ids,
                                                   const int* __restrict__ mask,
                                                   const float* __restrict__ emb) {
    __shared__ float2 sb[4][576];
    __shared__ float red[4][2];
    int tid = threadIdx.x;
    int grp = tid >> 6, t = tid & 63;
    int blk = blockIdx.x * 4 + grp;                 // global leaf index b*64+l
    int id = __ldg(ids + blk);
    int mk = __ldg(mask + blk);
    const float2* row = (const float2*)emb + (size_t)id * (PD / 2);

    float2 a[8];
    float ss = 0.f;
#pragma unroll
    for (int q = 0; q < 8; q++) {
        float2 v = row[t + 64 * q];
        if (mk <= 0) v = make_float2(0.f, 0.f);
        a[q] = v;
        ss += v.x * v.x + v.y * v.y;
    }
#pragma unroll
    for (int o = 16; o > 0; o >>= 1) ss += __shfl_xor_sync(0xffffffffu, ss, o);
    if ((t & 31) == 0) red[grp][t >> 5] = ss;
    __syncthreads();
    ss = red[grp][0] + red[grp][1];
    float inv = 1.f / (sqrtf(ss) + 1e-6f);

    int b = blk >> 6, l = blk & 63;
    size_t node = (size_t)b * PN + l;
    __nv_bfloat162* td2 = (__nv_bfloat162*)(g_tdb + node * PD);
#pragma unroll
    for (int q = 0; q < 8; q++) {
        a[q].x *= inv; a[q].y *= inv;
        td2[t + 64 * q] = __floats2bfloat162_rn(a[q].x, a[q].y);
    }
    fft512_reg<false>(a, sb[grp], t);

    float2* fd = g_fd + node * HB;
    float2* s = sb[grp];
#pragma unroll
    for (int q = 0; q < 4; q++) {
        int k = t + 64 * q;
        if (k == 0) {
            float2 z0 = SBP(s, 0);
            fd[0] = make_float2(z0.x + z0.y, z0.x - z0.y);
            float2 z = SBP(s, 256);
            fd[256] = make_float2(z.x, -z.y);
        } else {
            float2 zk = SBP(s, k), zk2 = SBP(s, 512 - k);
            float ex = 0.5f * (zk.x + zk2.x), ey = 0.5f * (zk.y - zk2.y);
            float dx = zk.x - zk2.x, dy = zk.y + zk2.y;
            float ox = 0.5f * dy, oy = -0.5f * dx;
            float2 w = g_w1024[k];
            float wx = w.x * ox - w.y * oy;
            float wy = w.x * oy + w.y * ox;
            fd[k]       = make_float2(ex + wx, ey + wy);
            fd[512 - k] = make_float2(ex - wx, -(ey - wy));
        }
    }
}

// ---------------------------------------------------------------------------
// Kernel 2: per-batch sequential composition on 512 half-spectrum bins, with
// FUSED inverse rfft: every 8 steps the block flushes the 8 buffered spectra
// through 8 parallel 64-thread radix-8 iFFTs and writes bf16 rows directly.
__global__ __launch_bounds__(512) void compose_kernel(const int* __restrict__ info) {
    __shared__ float2 sh[HB];          // last composed spectrum
    __shared__ float2 buf[8][576];     // batch spectra / iFFT scratch
    __shared__ float red[2][16];
    __shared__ int slotnode[8];
    int b = blockIdx.x, tid = threadIdx.x;
    const int lane = tid & 31, wrp = tid >> 5;
    const int grp = tid >> 6, gt = tid & 63;
    const int* bi = info + (size_t)b * PS * 3;
    float2* fdb = g_fd + (size_t)b * PN * HB;
    __nv_bfloat16* tdb_b = g_tdb + (size_t)b * PN * PD;

    int i0 = bi[0], i1 = bi[1], i2 = bi[2];
    float2 pl = fdb[(size_t)i0 * HB + tid];
    float2 pr = fdb[(size_t)i1 * HB + tid];
    int last = -1;
    for (int st = 0; st < PS; st++) {
        float2 fl = (i0 == last) ? sh[tid] : pl;
        float2 fr = (i1 == last) ? sh[tid] : pr;
        float2 c;
        float ss;
        if (tid == 0) {
            c = make_float2(fl.x * fr.x, fl.y * fr.y);
            ss = c.x * c.x + c.y * c.y;
        } else {
            c = make_float2(fl.x * fr.x + fl.y * fr.y,
                            fl.x * fr.y - fl.y * fr.x);
            ss = 2.f * (c.x * c.x + c.y * c.y);
        }
        int n0 = i0, n1 = i1, n2 = i2;
        if (st + 1 < PS) {
            n0 = bi[(st + 1) * 3 + 0];
            n1 = bi[(st + 1) * 3 + 1];
            n2 = bi[(st + 1) * 3 + 2];
            if (n0 != i2) pl = fdb[(size_t)n0 * HB + tid];
            if (n1 != i2) pr = fdb[(size_t)n1 * HB + tid];
        }
        float* rb = red[st & 1];
#pragma unroll
        for (int o = 16; o > 0; o >>= 1) ss += __shfl_xor_sync(0xffffffffu, ss, o);
        if (lane == 0) rb[wrp] = ss;
        __syncthreads();
        float tot = 0.f;
#pragma unroll
        for (int i = 0; i < 16; i++) tot += rb[i];

        float inv = 1.f / (sqrtf(tot * (1.f / (float)PD)) + 1e-6f);
        float2 cc = make_float2(c.x * inv, c.y * inv);
        sh[tid] = cc;
        buf[st & 7][tid] = cc;
        if (tid == 0) slotnode[st & 7] = i2;
        fdb[(size_t)i2 * HB + tid] = cc;
        last = i2; i0 = n0; i1 = n1; i2 = n2;

        // Flush: 8 parallel iFFTs (or 7 on the final partial batch).
        if ((st & 7) == 7 || st == PS - 1) {
            int cnt = (st & 7) + 1;
            __syncthreads();                        // buf + slotnode visible
            int node = slotnode[grp < cnt ? grp : 0];
            float2* gb = buf[grp];
            float2 a[8];
            irfft_load(gb, a, gt);
            __syncthreads();                        // reads done before scratch reuse
            fft512_reg<true>(a, gb, gt);            // (ends with __syncthreads)
            if (grp < cnt)
                irfft_store(gb, tdb_b + (size_t)node * PD, gt);
            __syncthreads();                        // writeout done before buf reuse
        }
    }
}

// ===========================================================================
// bf16 wmma GEMM: 128x128x32 tile, 8 warps (4x2) of 32x64, 3-stage cp.async
// ring, 60KB dynamic smem, 2 CTAs/SM. Coalesced float4 epilogue.
// ===========================================================================
#define BKG 32
#define LDKB 40
#define STG_ELEMS (128 * LDKB)

#define CP_ASYNC16(dst, src) \
    asm volatile("cp.async.cg.shared.global [%0], [%1], 16;\n" :: "r"(dst), "l"(src))
#define CP_COMMIT() asm volatile("cp.async.commit_group;\n" ::: "memory")
#define CP_WAIT(n)  asm volatile("cp.async.wait_group %0;\n" :: "n"(n) : "memory")

__device__ __forceinline__ uint32_t smem_u32(const void* p) {
    uint32_t a;
    asm("{ .reg .u64 t; cvta.to.shared.u64 t, %1; cvt.u32.u64 %0, t; }" : "=r"(a) : "l"(p));
    return a;
}

__global__ __launch_bounds__(256, 2)
void gemm_wmma_kernel(const float* __restrict__ bias,
                      float* __restrict__ out) {
    extern __shared__ __align__(16) char dsm[];
    __nv_bfloat16* As = (__nv_bfloat16*)dsm;
    __nv_bfloat16* Bs = As + 3 * STG_ELEMS;

    const int tid = threadIdx.x;
    const int wid = tid >> 5;
    const int lid = tid & 31;
    const int wr = wid & 3;
    const int wc = wid >> 2;
    const int m0 = blockIdx.y * 128;
    const int c0 = blockIdx.x * 128;
    const __nv_bfloat16* A = g_tdb;

    if (c0 + 128 > PC) {
        for (int st = 0; st < 3; st++)
            for (int idx = tid; idx < STG_ELEMS; idx += 256) {
                int row = idx / LDKB;
                if (c0 + row >= PC) Bs[st * STG_ELEMS + idx] = __float2bfloat16(0.f);
            }
    }
    __syncthreads();

    const uint32_t sAb = smem_u32(As);
    const uint32_t sBb = smem_u32(Bs);

    auto load_stage = [&](int stage, int kk) {
        uint32_t sA = sAb + (uint32_t)stage * STG_ELEMS * 2;
        uint32_t sB = sBb + (uint32_t)stage * STG_ELEMS * 2;
#pragma unroll
        for (int i = 0; i < 2; i++) {
            int idx = tid + i * 256;
            int row = idx >> 2, q = idx & 3;
            CP_ASYNC16(sA + (uint32_t)(row * LDKB + q * 8) * 2,
                       A + (size_t)(m0 + row) * PD + kk + q * 8);
        }
#pragma unroll
        for (int i = 0; i < 2; i++) {
            int idx = tid + i * 256;
            int row = idx >> 2, q = idx & 3;
            if (c0 + row < PC)
                CP_ASYNC16(sB + (uint32_t)(row * LDKB + q * 8) * 2,
                           g_wb + (size_t)(c0 + row) * PD + kk + q * 8);
        }
    };

    wmma::fragment<wmma::accumulator, 16, 16, 16, float> acc[2][4];
#pragma unroll
    for (int i = 0; i < 2; i++)
#pragma unroll
        for (int j = 0; j < 4; j++) wmma::fill_fragment(acc[i][j], 0.f);

    load_stage(0, 0);
    CP_COMMIT();
    load_stage(1, BKG);
    CP_COMMIT();

    const int NK = PD / BKG;
    for (int kt = 0; kt < NK; kt++) {
        if (kt + 1 < NK) { CP_WAIT(1); } else { CP_WAIT(0); }
        __syncthreads();
        if (kt + 2 < NK) {
            load_stage((kt + 2) % 3, (kt + 2) * BKG);
            CP_COMMIT();
        }
        const __nv_bfloat16* Ac = As + (kt % 3) * STG_ELEMS;
        const __nv_bfloat16* Bc = Bs + (kt % 3) * STG_ELEMS;
#pragma unroll
        for (int ks = 0; ks < 2; ks++) {
            wmma::fragment<wmma::matrix_a, 16, 16, 16, __nv_bfloat16, wmma::row_major> af[2];
            wmma::fragment<wmma::matrix_b, 16, 16, 16, __nv_bfloat16, wmma::col_major> bf[4];
#pragma unroll
            for (int i = 0; i < 2; i++)
                wmma::load_matrix_sync(af[i], Ac + (wr * 32 + i * 16) * LDKB + ks * 16, LDKB);
#pragma unroll
            for (int j = 0; j < 4; j++)
                wmma::load_matrix_sync(bf[j], Bc + (wc * 64 + j * 16) * LDKB + ks * 16, LDKB);
#pragma unroll
            for (int i = 0; i < 2; i++)
#pragma unroll
                for (int j = 0; j < 4; j++)
                    wmma::mma_sync(acc[i][j], af[i], bf[j], acc[i][j]);
        }
    }
    __syncthreads();

    // Epilogue: per warp stage a full 16x64 half (4 fragments, stride 68),
    // then 256B-contiguous float4 stores with bias + sigmoid.
    float* stage = (float*)dsm + wid * 1088;
    const int r = lid >> 1;
    const int hcol = (lid & 1) * 32;
#pragma unroll
    for (int i = 0; i < 2; i++) {
#pragma unroll
        for (int j = 0; j < 4; j++)
            wmma::store_matrix_sync(stage + j * 16, acc[i][j], 68, wmma::mem_row_major);
        __syncwarp();
        int m = m0 + wr * 32 + i * 16 + r;
        int cbase = c0 + wc * 64 + hcol;
        float* orow = out + (size_t)m * PC;
        const float* srow = stage + r * 68 + hcol;
#pragma unroll
        for (int k = 0; k < 8; k++) {
            int c = cbase + 4 * k;
            if (c < PC) {
                float4 v = *(const float4*)(srow + 4 * k);
                float4 bb = *(const float4*)(bias + c);
                float4 o;
                o.x = 1.f / (1.f + __expf(-(v.x + bb.x)));
                o.y = 1.f / (1.f + __expf(-(v.y + bb.y)));
                o.z = 1.f / (1.f + __expf(-(v.z + bb.z)));
                o.w = 1.f / (1.f + __expf(-(v.w + bb.w)));
                *(float4*)(orow + c) = o;
            }
        }
        __syncwarp();
    }
}

#define GEMM_SMEM (6 * STG_ELEMS * 2)   // 61440 bytes

// ---------------------------------------------------------------------------
extern "C" void kernel_launch(void* const* d_in, const int* in_sizes, int n_in,
                              void* d_out, int out_size) {
    const int*   ids  = (const int*)d_in[0];
    const int*   mask = (const int*)d_in[1];
    const int*   info = (const int*)d_in[2];
    const float* emb  = (const float*)d_in[3];
    const float* W    = (const float*)d_in[4];
    const float* bias = (const float*)d_in[5];
    float* out = (float*)d_out;

    setup_kernel<<<2 + PC, 256>>>(W);
    leaf_kernel<<<PB * PL / 4, 256>>>(ids, mask, emb);
    compose_kernel<<<PB, 512>>>(info);

    cudaFuncSetAttribute(gemm_wmma_kernel,
                         cudaFuncAttributeMaxDynamicSharedMemorySize, GEMM_SMEM);
    dim3 gg((PC + 127) / 128, (PB * PN) / 128);   // 4 x 254
    gemm_wmma_kernel<<<gg, 256, GEMM_SMEM>>>(bias, out);
}

// round 14
// speedup vs baseline: 1.0063x; 1.0063x over previous
#include <cuda_runtime.h>
#include <cuda_bf16.h>
#include <mma.h>
#include <math.h>
#include <cstdint>

using namespace nvcuda;

// Problem constants
#define PB 256      // batch
#define PL 64       // leaves
#define PD 1024     // dim
#define PC 500      // classes
#define PN 127      // nodes = 2L-1
#define PS 63       // steps = L-1
#define HB 512      // half-spectrum bins stored per node

// Scratch
static __device__ __nv_bfloat16 g_tdb[(size_t)PB * PN * PD];  // 66 MB (GEMM A)
static __device__ float2        g_fd[(size_t)PB * PN * HB];   // 133 MB (half spectra)
static __device__ __nv_bfloat16 g_wb[(size_t)PC * PD];        // 1 MB  (W in bf16)
static __device__ float2        g_w1024[512];                 // W1024^k (untangle)
static __device__ float2        g_w512[512];                  // W512^j  (FFT twiddles)

// ---------------------------------------------------------------------------
// Setup: twiddle tables + W bf16 conversion.
__global__ void setup_kernel(const float* __restrict__ W) {
    int g = blockIdx.x;
    if (g == 0) {
        for (int i = threadIdx.x; i < 512; i += 256) {
            float sn, cs;
            sincosf(-6.283185307179586f * (float)i / 1024.f, &sn, &cs);
            g_w1024[i] = make_float2(cs, sn);
        }
    } else if (g == 1) {
        for (int i = threadIdx.x; i < 512; i += 256) {
            float sn, cs;
            sincosf(-6.283185307179586f * (float)i / 512.f, &sn, &cs);
            g_w512[i] = make_float2(cs, sn);
        }
    } else {
        int i = (g - 2) * 1024 + threadIdx.x * 4;
        float4 v = *(const float4*)(W + i);
        __nv_bfloat16* o = g_wb + i;
        o[0] = __float2bfloat16(v.x);
        o[1] = __float2bfloat16(v.y);
        o[2] = __float2bfloat16(v.z);
        o[3] = __float2bfloat16(v.w);
    }
}

// ---------------------------------------------------------------------------
// Complex helpers
__device__ __forceinline__ float2 cadd(float2 a, float2 b) { return make_float2(a.x + b.x, a.y + b.y); }
__device__ __forceinline__ float2 csub(float2 a, float2 b) { return make_float2(a.x - b.x, a.y - b.y); }
__device__ __forceinline__ float2 cmul(float2 a, float2 b) {
    return make_float2(fmaf(a.x, b.x, -a.y * b.y), fmaf(a.x, b.y, a.y * b.x));
}
template<bool INV>
__device__ __forceinline__ float2 crot(float2 a) {   // * (-i) fwd, * (+i) inv
    return INV ? make_float2(-a.y, a.x) : make_float2(a.y, -a.x);
}

// In-register 8-point DFT, natural-order in/out.
template<bool INV>
__device__ __forceinline__ void fft8(float2* a) {
    const float r = 0.70710678118654752440f;
    const float2 w1 = INV ? make_float2(r, r)  : make_float2(r, -r);
    const float2 w3 = INV ? make_float2(-r, r) : make_float2(-r, -r);
    float2 b0 = cadd(a[0], a[4]), b4 = csub(a[0], a[4]);
    float2 b1 = cadd(a[1], a[5]), b5 = cmul(csub(a[1], a[5]), w1);
    float2 b2 = cadd(a[2], a[6]), b6 = crot<INV>(csub(a[2], a[6]));
    float2 b3 = cadd(a[3], a[7]), b7 = cmul(csub(a[3], a[7]), w3);
    float2 c0 = cadd(b0, b2), c2 = csub(b0, b2);
    float2 c1 = cadd(b1, b3), c3 = crot<INV>(csub(b1, b3));
    float2 c4 = cadd(b4, b6), c6 = csub(b4, b6);
    float2 c5 = cadd(b5, b7), c7 = crot<INV>(csub(b5, b7));
    a[0] = cadd(c0, c1); a[4] = csub(c0, c1);
    a[2] = cadd(c2, c3); a[6] = csub(c2, c3);
    a[1] = cadd(c4, c5); a[5] = csub(c4, c5);
    a[3] = cadd(c6, c7); a[7] = csub(c6, c7);
}

// Padded natural-order index: p(n) = n + n/8 (row stride 9, max 574 < 576).
#define SBP(s, n) ((s)[(n) + ((n) >> 3)])

// 512-pt complex FFT, radix-8^3, 64 threads per FFT, 8 values in registers.
template<bool INV>
__device__ __forceinline__ void fft512_reg(float2* a, float2* sb, int t) {
    fft8<INV>(a);
    sb[t] = a[0];
#pragma unroll
    for (int k1 = 1; k1 < 8; k1++) {
        float2 w = g_w512[t * k1];
        if (INV) w.y = -w.y;
        sb[72 * k1 + t] = cmul(a[k1], w);
    }
    __syncthreads();
    const int k1 = t >> 3, m2 = t & 7;
    {
        const float2* base = sb + 72 * k1 + m2;
#pragma unroll
        for (int m1 = 0; m1 < 8; m1++) a[m1] = base[8 * m1];
    }
    __syncthreads();
    fft8<INV>(a);
    sb[72 * k1 + m2] = a[0];
#pragma unroll
    for (int j1 = 1; j1 < 8; j1++) {
        float2 w = g_w512[8 * m2 * j1];
        if (INV) w.y = -w.y;
        sb[72 * k1 + 9 * j1 + m2] = cmul(a[j1], w);
    }
    __syncthreads();
    const int j1 = t & 7;
    {
        const float2* base = sb + 72 * k1 + 9 * j1;
#pragma unroll
        for (int m = 0; m < 8; m++) a[m] = base[m];
    }
    __syncthreads();
    fft8<INV>(a);
#pragma unroll
    for (int j2 = 0; j2 < 8; j2++) {
        int n = k1 + 8 * j1 + 64 * j2;
        SBP(sb, n) = a[j2];
    }
    __syncthreads();
}

// ---------------------------------------------------------------------------
// Kernel 1: leaf gather + mask + L2-normalize -> bf16 TD; rfft -> half FD.
__global__ __launch_bounds__(256) void leaf_kernel(const int* __restrict__ ids,
                                                   const int* __restrict__ mask,
                                                   const float* __restrict__ emb) {
    __shared__ float2 sb[4][576];
    __shared__ float red[4][2];
    int tid = threadIdx.x;
    int grp = tid >> 6, t = tid & 63;
    int blk = blockIdx.x * 4 + grp;                 // global leaf index b*64+l
    int id = __ldg(ids + blk);
    int mk = __ldg(mask + blk);
    const float2* row = (const float2*)emb + (size_t)id * (PD / 2);

    float2 a[8];
    float ss = 0.f;
#pragma unroll
    for (int q = 0; q < 8; q++) {
        float2 v = row[t + 64 * q];
        if (mk <= 0) v = make_float2(0.f, 0.f);
        a[q] = v;
        ss += v.x * v.x + v.y * v.y;
    }
#pragma unroll
    for (int o = 16; o > 0; o >>= 1) ss += __shfl_xor_sync(0xffffffffu, ss, o);
    if ((t & 31) == 0) red[grp][t >> 5] = ss;
    __syncthreads();
    ss = red[grp][0] + red[grp][1];
    float inv = 1.f / (sqrtf(ss) + 1e-6f);

    int b = blk >> 6, l = blk & 63;
    size_t node = (size_t)b * PN + l;
    __nv_bfloat162* td2 = (__nv_bfloat162*)(g_tdb + node * PD);
#pragma unroll
    for (int q = 0; q < 8; q++) {
        a[q].x *= inv; a[q].y *= inv;
        td2[t + 64 * q] = __floats2bfloat162_rn(a[q].x, a[q].y);
    }
    fft512_reg<false>(a, sb[grp], t);

    float2* fd = g_fd + node * HB;
    float2* s = sb[grp];
#pragma unroll
    for (int q = 0; q < 4; q++) {
        int k = t + 64 * q;
        if (k == 0) {
            float2 z0 = SBP(s, 0);
            fd[0] = make_float2(z0.x + z0.y, z0.x - z0.y);
            float2 z = SBP(s, 256);
            fd[256] = make_float2(z.x, -z.y);
        } else {
            float2 zk = SBP(s, k), zk2 = SBP(s, 512 - k);
            float ex = 0.5f * (zk.x + zk2.x), ey = 0.5f * (zk.y - zk2.y);
            float dx = zk.x - zk2.x, dy = zk.y + zk2.y;
            float ox = 0.5f * dy, oy = -0.5f * dx;
            float2 w = g_w1024[k];
            float wx = w.x * ox - w.y * oy;
            float wy = w.x * oy + w.y * ox;
            fd[k]       = make_float2(ex + wx, ey + wy);
            fd[512 - k] = make_float2(ex - wx, -(ey - wy));
        }
    }
}

// ---------------------------------------------------------------------------
// Kernel 2: per-batch sequential composition on 512 half-spectrum bins.
__global__ void compose_kernel(const int* __restrict__ info) {
    __shared__ float2 sh[HB];
    __shared__ float red[2][16];
    int b = blockIdx.x, tid = threadIdx.x;
    const int lane = tid & 31, wrp = tid >> 5;
    const int* bi = info + (size_t)b * PS * 3;
    float2* fdb = g_fd + (size_t)b * PN * HB;

    int i0 = bi[0], i1 = bi[1], i2 = bi[2];
    float2 pl = fdb[(size_t)i0 * HB + tid];
    float2 pr = fdb[(size_t)i1 * HB + tid];
    int last = -1;
    for (int st = 0; st < PS; st++) {
        float2 fl = (i0 == last) ? sh[tid] : pl;
        float2 fr = (i1 == last) ? sh[tid] : pr;
        float2 c;
        float ss;
        if (tid == 0) {
            c = make_float2(fl.x * fr.x, fl.y * fr.y);
            ss = c.x * c.x + c.y * c.y;
        } else {
            c = make_float2(fl.x * fr.x + fl.y * fr.y,
                            fl.x * fr.y - fl.y * fr.x);
            ss = 2.f * (c.x * c.x + c.y * c.y);
        }
        int n0 = i0, n1 = i1, n2 = i2;
        if (st + 1 < PS) {
            n0 = bi[(st + 1) * 3 + 0];
            n1 = bi[(st + 1) * 3 + 1];
            n2 = bi[(st + 1) * 3 + 2];
            if (n0 != i2) pl = fdb[(size_t)n0 * HB + tid];
            if (n1 != i2) pr = fdb[(size_t)n1 * HB + tid];
        }
        float* rb = red[st & 1];
#pragma unroll
        for (int o = 16; o > 0; o >>= 1) ss += __shfl_xor_sync(0xffffffffu, ss, o);
        if (lane == 0) rb[wrp] = ss;
        __syncthreads();
        float tot = 0.f;
#pragma unroll
        for (int i = 0; i < 16; i++) tot += rb[i];

        float inv = 1.f / (sqrtf(tot * (1.f / (float)PD)) + 1e-6f);
        float2 cc = make_float2(c.x * inv, c.y * inv);
        sh[tid] = cc;
        fdb[(size_t)i2 * HB + tid] = cc;
        last = i2; i0 = n0; i1 = n1; i2 = n2;
    }
}

// ---------------------------------------------------------------------------
// Kernel 3: inverse rfft of internal nodes -> bf16 TD.
__global__ __launch_bounds__(256) void irfft_kernel() {
    __shared__ float2 sb[4][576];
    int tid = threadIdx.x;
    int grp = tid >> 6, t = tid & 63;
    int blk = blockIdx.x * 4 + grp;                 // 0..16127
    int b = blk / PS, s0 = blk - b * PS;
    size_t node = (size_t)b * PN + PL + s0;
    const float2* fd = g_fd + node * HB;

    float2 a[8];
#pragma unroll
    for (int q = 0; q < 8; q++) {
        int k = t + 64 * q;
        float2 z;
        if (k == 0) {
            float2 p = fd[0];
            z = make_float2(0.5f * (p.x + p.y), 0.5f * (p.x - p.y));
        } else if (k == 256) {
            float2 x = fd[256];
            z = make_float2(x.x, -x.y);
        } else if (k < 256) {
            float2 Xk = fd[k], Xk2 = fd[512 - k];
            float ex = 0.5f * (Xk.x + Xk2.x), ey = 0.5f * (Xk.y - Xk2.y);
            float dx = Xk.x - Xk2.x, dy = Xk.y + Xk2.y;
            float2 w = g_w1024[k];
            float ox = 0.5f * (dx * w.x + dy * w.y);
            float oy = 0.5f * (dy * w.x - dx * w.y);
            z = make_float2(ex - oy, ey + ox);
        } else {
            int kk = 512 - k;
            float2 Xk = fd[kk], Xk2 = fd[k];
            float ex = 0.5f * (Xk.x + Xk2.x), ey = 0.5f * (Xk.y - Xk2.y);
            float dx = Xk.x - Xk2.x, dy = Xk.y + Xk2.y;
            float2 w = g_w1024[kk];
            float ox = 0.5f * (dx * w.x + dy * w.y);
            float oy = 0.5f * (dy * w.x - dx * w.y);
            z = make_float2(ex + oy, ox - ey);
        }
        a[q] = z;
    }
    fft512_reg<true>(a, sb[grp], t);

    const float sc = 1.f / 512.f;
    int4* td4 = (int4*)(g_tdb + node * PD);
    float2* s = sb[grp];
#pragma unroll
    for (int h = 0; h < 2; h++) {
        union { int4 v; __nv_bfloat162 e[4]; } u;
#pragma unroll
        for (int e2 = 0; e2 < 4; e2++) {
            float2 z = s[9 * t + h * 4 + e2];
            u.e[e2] = __floats2bfloat162_rn(z.x * sc, z.y * sc);
        }
        td4[2 * t + h] = u.v;
    }
}

// ===========================================================================
// bf16 wmma GEMM v4: 64x128x32 block tile, 128 threads (4 warps, 2x2 of
// 32x64), 3-stage cp.async ring, 45KB smem -> 4 independent CTAs/SM.
// ===========================================================================
#define BKG 32
#define LDKB 40
#define A_STG (64 * LDKB)     // 2560 elems
#define B_STG (128 * LDKB)    // 5120 elems

#define CP_ASYNC16(dst, src) \
    asm volatile("cp.async.cg.shared.global [%0], [%1], 16;\n" :: "r"(dst), "l"(src))
#define CP_COMMIT() asm volatile("cp.async.commit_group;\n" ::: "memory")
#define CP_WAIT(n)  asm volatile("cp.async.wait_group %0;\n" :: "n"(n) : "memory")

__device__ __forceinline__ uint32_t smem_u32(const void* p) {
    uint32_t a;
    asm("{ .reg .u64 t; cvta.to.shared.u64 t, %1; cvt.u32.u64 %0, t; }" : "=r"(a) : "l"(p));
    return a;
}

__global__ __launch_bounds__(128, 4)
void gemm_wmma_kernel(const float* __restrict__ bias,
                      float* __restrict__ out) {
    extern __shared__ __align__(16) char dsm[];
    __nv_bfloat16* As = (__nv_bfloat16*)dsm;        // 3 stages
    __nv_bfloat16* Bs = As + 3 * A_STG;

    const int tid = threadIdx.x;
    const int wid = tid >> 5;
    const int lid = tid & 31;
    const int wr = wid & 1;          // warp row (0..1) -> 32 rows each
    const int wc = wid >> 1;         // warp col (0..1) -> 64 cols each
    const int m0 = blockIdx.y * 64;
    const int c0 = blockIdx.x * 128;
    const __nv_bfloat16* A = g_tdb;

    // Zero B rows beyond PC in all stages (cp.async never writes them).
    if (c0 + 128 > PC) {
        for (int st = 0; st < 3; st++)
            for (int idx = tid; idx < B_STG; idx += 128) {
                int row = idx / LDKB;
                if (c0 + row >= PC) Bs[st * B_STG + idx] = __float2bfloat16(0.f);
            }
    }
    __syncthreads();

    const uint32_t sAb = smem_u32(As);
    const uint32_t sBb = smem_u32(Bs);

    auto load_stage = [&](int stage, int kk) {
        uint32_t sA = sAb + (uint32_t)stage * A_STG * 2;
        uint32_t sB = sBb + (uint32_t)stage * B_STG * 2;
#pragma unroll
        for (int i = 0; i < 2; i++) {               // A: 64 rows x 4 chunks
            int idx = tid + i * 128;
            int row = idx >> 2, q = idx & 3;
            CP_ASYNC16(sA + (uint32_t)(row * LDKB + q * 8) * 2,
                       A + (size_t)(m0 + row) * PD + kk + q * 8);
        }
#pragma unroll
        for (int i = 0; i < 4; i++) {               // B: 128 rows x 4 chunks
            int idx = tid + i * 128;
            int row = idx >> 2, q = idx & 3;
            if (c0 + row < PC)
                CP_ASYNC16(sB + (uint32_t)(row * LDKB + q * 8) * 2,
                           g_wb + (size_t)(c0 + row) * PD + kk + q * 8);
        }
    };

    wmma::fragment<wmma::accumulator, 16, 16, 16, float> acc[2][4];
#pragma unroll
    for (int i = 0; i < 2; i++)
#pragma unroll
        for (int j = 0; j < 4; j++) wmma::fill_fragment(acc[i][j], 0.f);

    load_stage(0, 0);
    CP_COMMIT();
    load_stage(1, BKG);
    CP_COMMIT();

    const int NK = PD / BKG;   // 32
    for (int kt = 0; kt < NK; kt++) {
        if (kt + 1 < NK) { CP_WAIT(1); } else { CP_WAIT(0); }
        __syncthreads();
        if (kt + 2 < NK) {
            load_stage((kt + 2) % 3, (kt + 2) * BKG);
            CP_COMMIT();
        }
        const __nv_bfloat16* Ac = As + (kt % 3) * A_STG;
        const __nv_bfloat16* Bc = Bs + (kt % 3) * B_STG;
#pragma unroll
        for (int ks = 0; ks < 2; ks++) {
            wmma::fragment<wmma::matrix_a, 16, 16, 16, __nv_bfloat16, wmma::row_major> af[2];
            wmma::fragment<wmma::matrix_b, 16, 16, 16, __nv_bfloat16, wmma::col_major> bf[4];
#pragma unroll
            for (int i = 0; i < 2; i++)
                wmma::load_matrix_sync(af[i], Ac + (wr * 32 + i * 16) * LDKB + ks * 16, LDKB);
#pragma unroll
            for (int j = 0; j < 4; j++)
                wmma::load_matrix_sync(bf[j], Bc + (wc * 64 + j * 16) * LDKB + ks * 16, LDKB);
#pragma unroll
            for (int i = 0; i < 2; i++)
#pragma unroll
                for (int j = 0; j < 4; j++)
                    wmma::mma_sync(acc[i][j], af[i], bf[j], acc[i][j]);
        }
    }
    __syncthreads();

    // Epilogue: per warp stage a 16x64 half (4 fragments, stride 68), then
    // 256B-contiguous float4 stores with bias + sigmoid.
    float* stage = (float*)dsm + wid * 1088;       // 4*1088*4B = 17KB < smem
    const int r = lid >> 1;
    const int hcol = (lid & 1) * 32;
#pragma unroll
    for (int i = 0; i < 2; i++) {
#pragma unroll
        for (int j = 0; j < 4; j++)
            wmma::store_matrix_sync(stage + j * 16, acc[i][j], 68, wmma::mem_row_major);
        __syncwarp();
        int m = m0 + wr * 32 + i * 16 + r;
        int cbase = c0 + wc * 64 + hcol;
        float* orow = out + (size_t)m * PC;
        const float* srow = stage + r * 68 + hcol;
#pragma unroll
        for (int k = 0; k < 8; k++) {
            int c = cbase + 4 * k;
            if (c < PC) {
                float4 v = *(const float4*)(srow + 4 * k);
                float4 bb = *(const float4*)(bias + c);
                float4 o;
                o.x = 1.f / (1.f + __expf(-(v.x + bb.x)));
                o.y = 1.f / (1.f + __expf(-(v.y + bb.y)));
                o.z = 1.f / (1.f + __expf(-(v.z + bb.z)));
                o.w = 1.f / (1.f + __expf(-(v.w + bb.w)));
                *(float4*)(orow + c) = o;
            }
        }
        __syncwarp();
    }
}

#define GEMM_SMEM ((3 * A_STG + 3 * B_STG) * 2)   // 46080 bytes

// ---------------------------------------------------------------------------
extern "C" void kernel_launch(void* const* d_in, const int* in_sizes, int n_in,
                              void* d_out, int out_size) {
    const int*   ids  = (const int*)d_in[0];
    const int*   mask = (const int*)d_in[1];
    const int*   info = (const int*)d_in[2];
    const float* emb  = (const float*)d_in[3];
    const float* W    = (const float*)d_in[4];
    const float* bias = (const float*)d_in[5];
    float* out = (float*)d_out;

    setup_kernel<<<2 + PC, 256>>>(W);
    leaf_kernel<<<PB * PL / 4, 256>>>(ids, mask, emb);
    compose_kernel<<<PB, 512>>>(info);
    irfft_kernel<<<PB * PS / 4, 256>>>();

    cudaFuncSetAttribute(gemm_wmma_kernel,
                         cudaFuncAttributeMaxDynamicSharedMemorySize, GEMM_SMEM);
    dim3 gg((PC + 127) / 128, (PB * PN) / 64);   // 4 x 508
    gemm_wmma_kernel<<<gg, 128, GEMM_SMEM>>>(bias, out);
}

// round 15
// speedup vs baseline: 1.0266x; 1.0201x over previous
#include <cuda_runtime.h>
#include <cuda_bf16.h>
#include <mma.h>
#include <math.h>
#include <cstdint>

using namespace nvcuda;

// Problem constants
#define PB 256      // batch
#define PL 64       // leaves
#define PD 1024     // dim
#define PC 500      // classes
#define PN 127      // nodes = 2L-1
#define PS 63       // steps = L-1
#define HB 512      // half-spectrum bins stored per node

// Scratch
static __device__ __nv_bfloat16 g_tdb[(size_t)PB * PN * PD];  // 66 MB (GEMM A)
static __device__ float2        g_fd[(size_t)PB * PN * HB];   // 133 MB (half spectra)
static __device__ __nv_bfloat16 g_wb[(size_t)PC * PD];        // 1 MB  (W in bf16)
static __device__ float2        g_w1024[512];                 // W1024^k (untangle)
static __device__ float2        g_w512[512];                  // W512^j  (FFT twiddles)

// ---------------------------------------------------------------------------
// Setup: twiddle tables + W bf16 conversion.
__global__ void setup_kernel(const float* __restrict__ W) {
    int g = blockIdx.x;
    if (g == 0) {
        for (int i = threadIdx.x; i < 512; i += 256) {
            float sn, cs;
            sincosf(-6.283185307179586f * (float)i / 1024.f, &sn, &cs);
            g_w1024[i] = make_float2(cs, sn);
        }
    } else if (g == 1) {
        for (int i = threadIdx.x; i < 512; i += 256) {
            float sn, cs;
            sincosf(-6.283185307179586f * (float)i / 512.f, &sn, &cs);
            g_w512[i] = make_float2(cs, sn);
        }
    } else {
        int i = (g - 2) * 1024 + threadIdx.x * 4;
        float4 v = *(const float4*)(W + i);
        __nv_bfloat16* o = g_wb + i;
        o[0] = __float2bfloat16(v.x);
        o[1] = __float2bfloat16(v.y);
        o[2] = __float2bfloat16(v.z);
        o[3] = __float2bfloat16(v.w);
    }
}

// ---------------------------------------------------------------------------
// Complex helpers
__device__ __forceinline__ float2 cadd(float2 a, float2 b) { return make_float2(a.x + b.x, a.y + b.y); }
__device__ __forceinline__ float2 csub(float2 a, float2 b) { return make_float2(a.x - b.x, a.y - b.y); }
__device__ __forceinline__ float2 cmul(float2 a, float2 b) {
    return make_float2(fmaf(a.x, b.x, -a.y * b.y), fmaf(a.x, b.y, a.y * b.x));
}
template<bool INV>
__device__ __forceinline__ float2 crot(float2 a) {   // * (-i) fwd, * (+i) inv
    return INV ? make_float2(-a.y, a.x) : make_float2(a.y, -a.x);
}

// In-register 8-point DFT, natural-order in/out.
template<bool INV>
__device__ __forceinline__ void fft8(float2* a) {
    const float r = 0.70710678118654752440f;
    const float2 w1 = INV ? make_float2(r, r)  : make_float2(r, -r);
    const float2 w3 = INV ? make_float2(-r, r) : make_float2(-r, -r);
    float2 b0 = cadd(a[0], a[4]), b4 = csub(a[0], a[4]);
    float2 b1 = cadd(a[1], a[5]), b5 = cmul(csub(a[1], a[5]), w1);
    float2 b2 = cadd(a[2], a[6]), b6 = crot<INV>(csub(a[2], a[6]));
    float2 b3 = cadd(a[3], a[7]), b7 = cmul(csub(a[3], a[7]), w3);
    float2 c0 = cadd(b0, b2), c2 = csub(b0, b2);
    float2 c1 = cadd(b1, b3), c3 = crot<INV>(csub(b1, b3));
    float2 c4 = cadd(b4, b6), c6 = csub(b4, b6);
    float2 c5 = cadd(b5, b7), c7 = crot<INV>(csub(b5, b7));
    a[0] = cadd(c0, c1); a[4] = csub(c0, c1);
    a[2] = cadd(c2, c3); a[6] = csub(c2, c3);
    a[1] = cadd(c4, c5); a[5] = csub(c4, c5);
    a[3] = cadd(c6, c7); a[7] = csub(c6, c7);
}

// Padded natural-order index: p(n) = n + n/8 (row stride 9, max 574 < 576).
#define SBP(s, n) ((s)[(n) + ((n) >> 3)])

// 512-pt complex FFT, radix-8^3, 64 threads (one block), 8 values in regs.
template<bool INV>
__device__ __forceinline__ void fft512_reg(float2* a, float2* sb, int t) {
    fft8<INV>(a);
    sb[t] = a[0];
#pragma unroll
    for (int k1 = 1; k1 < 8; k1++) {
        float2 w = g_w512[t * k1];
        if (INV) w.y = -w.y;
        sb[72 * k1 + t] = cmul(a[k1], w);
    }
    __syncthreads();
    const int k1 = t >> 3, m2 = t & 7;
    {
        const float2* base = sb + 72 * k1 + m2;
#pragma unroll
        for (int m1 = 0; m1 < 8; m1++) a[m1] = base[8 * m1];
    }
    __syncthreads();
    fft8<INV>(a);
    sb[72 * k1 + m2] = a[0];
#pragma unroll
    for (int j1 = 1; j1 < 8; j1++) {
        float2 w = g_w512[8 * m2 * j1];
        if (INV) w.y = -w.y;
        sb[72 * k1 + 9 * j1 + m2] = cmul(a[j1], w);
    }
    __syncthreads();
    const int j1 = t & 7;
    {
        const float2* base = sb + 72 * k1 + 9 * j1;
#pragma unroll
        for (int m = 0; m < 8; m++) a[m] = base[m];
    }
    __syncthreads();
    fft8<INV>(a);
#pragma unroll
    for (int j2 = 0; j2 < 8; j2++) {
        int n = k1 + 8 * j1 + 64 * j2;
        SBP(sb, n) = a[j2];
    }
    __syncthreads();
}

// ---------------------------------------------------------------------------
// Kernel 1: leaf gather + mask + L2-normalize -> bf16 TD; rfft -> half FD.
// One leaf per 64-thread block (cheap 2-warp barriers, fine reg quantization).
__global__ __launch_bounds__(64) void leaf_kernel(const int* __restrict__ ids,
                                                  const int* __restrict__ mask,
                                                  const float* __restrict__ emb) {
    __shared__ float2 sb[576];
    __shared__ float red[2];
    int t = threadIdx.x;
    int blk = blockIdx.x;                           // global leaf index b*64+l
    int id = __ldg(ids + blk);
    int mk = __ldg(mask + blk);
    const float2* row = (const float2*)emb + (size_t)id * (PD / 2);

    float2 a[8];
    float ss = 0.f;
#pragma unroll
    for (int q = 0; q < 8; q++) {
        float2 v = row[t + 64 * q];
        if (mk <= 0) v = make_float2(0.f, 0.f);
        a[q] = v;
        ss += v.x * v.x + v.y * v.y;
    }
#pragma unroll
    for (int o = 16; o > 0; o >>= 1) ss += __shfl_xor_sync(0xffffffffu, ss, o);
    if ((t & 31) == 0) red[t >> 5] = ss;
    __syncthreads();
    ss = red[0] + red[1];
    float inv = 1.f / (sqrtf(ss) + 1e-6f);

    int b = blk >> 6, l = blk & 63;
    size_t node = (size_t)b * PN + l;
    __nv_bfloat162* td2 = (__nv_bfloat162*)(g_tdb + node * PD);
#pragma unroll
    for (int q = 0; q < 8; q++) {
        a[q].x *= inv; a[q].y *= inv;
        td2[t + 64 * q] = __floats2bfloat162_rn(a[q].x, a[q].y);
    }
    fft512_reg<false>(a, sb, t);

    float2* fd = g_fd + node * HB;
    float2* s = sb;
#pragma unroll
    for (int q = 0; q < 4; q++) {
        int k = t + 64 * q;
        if (k == 0) {
            float2 z0 = SBP(s, 0);
            fd[0] = make_float2(z0.x + z0.y, z0.x - z0.y);
            float2 z = SBP(s, 256);
            fd[256] = make_float2(z.x, -z.y);
        } else {
            float2 zk = SBP(s, k), zk2 = SBP(s, 512 - k);
            float ex = 0.5f * (zk.x + zk2.x), ey = 0.5f * (zk.y - zk2.y);
            float dx = zk.x - zk2.x, dy = zk.y + zk2.y;
            float ox = 0.5f * dy, oy = -0.5f * dx;
            float2 w = g_w1024[k];
            float wx = w.x * ox - w.y * oy;
            float wy = w.x * oy + w.y * ox;
            fd[k]       = make_float2(ex + wx, ey + wy);
            fd[512 - k] = make_float2(ex - wx, -(ey - wy));
        }
    }
}

// ---------------------------------------------------------------------------
// Kernel 2: per-batch sequential composition on 512 half-spectrum bins.
__global__ void compose_kernel(const int* __restrict__ info) {
    __shared__ float2 sh[HB];
    __shared__ float red[2][16];
    int b = blockIdx.x, tid = threadIdx.x;
    const int lane = tid & 31, wrp = tid >> 5;
    const int* bi = info + (size_t)b * PS * 3;
    float2* fdb = g_fd + (size_t)b * PN * HB;

    int i0 = bi[0], i1 = bi[1], i2 = bi[2];
    float2 pl = fdb[(size_t)i0 * HB + tid];
    float2 pr = fdb[(size_t)i1 * HB + tid];
    int last = -1;
    for (int st = 0; st < PS; st++) {
        float2 fl = (i0 == last) ? sh[tid] : pl;
        float2 fr = (i1 == last) ? sh[tid] : pr;
        float2 c;
        float ss;
        if (tid == 0) {
            c = make_float2(fl.x * fr.x, fl.y * fr.y);
            ss = c.x * c.x + c.y * c.y;
        } else {
            c = make_float2(fl.x * fr.x + fl.y * fr.y,
                            fl.x * fr.y - fl.y * fr.x);
            ss = 2.f * (c.x * c.x + c.y * c.y);
        }
        int n0 = i0, n1 = i1, n2 = i2;
        if (st + 1 < PS) {
            n0 = bi[(st + 1) * 3 + 0];
            n1 = bi[(st + 1) * 3 + 1];
            n2 = bi[(st + 1) * 3 + 2];
            if (n0 != i2) pl = fdb[(size_t)n0 * HB + tid];
            if (n1 != i2) pr = fdb[(size_t)n1 * HB + tid];
        }
        float* rb = red[st & 1];
#pragma unroll
        for (int o = 16; o > 0; o >>= 1) ss += __shfl_xor_sync(0xffffffffu, ss, o);
        if (lane == 0) rb[wrp] = ss;
        __syncthreads();
        float tot = 0.f;
#pragma unroll
        for (int i = 0; i < 16; i++) tot += rb[i];

        float inv = 1.f / (sqrtf(tot * (1.f / (float)PD)) + 1e-6f);
        float2 cc = make_float2(c.x * inv, c.y * inv);
        sh[tid] = cc;
        fdb[(size_t)i2 * HB + tid] = cc;
        last = i2; i0 = n0; i1 = n1; i2 = n2;
    }
}

// ---------------------------------------------------------------------------
// Kernel 3: inverse rfft of internal nodes -> bf16 TD. One node per 64-thread
// block.
__global__ __launch_bounds__(64) void irfft_kernel() {
    __shared__ float2 sb[576];
    int t = threadIdx.x;
    int blk = blockIdx.x;                           // 0..16127
    int b = blk / PS, s0 = blk - b * PS;
    size_t node = (size_t)b * PN + PL + s0;
    const float2* fd = g_fd + node * HB;

    float2 a[8];
#pragma unroll
    for (int q = 0; q < 8; q++) {
        int k = t + 64 * q;
        float2 z;
        if (k == 0) {
            float2 p = fd[0];
            z = make_float2(0.5f * (p.x + p.y), 0.5f * (p.x - p.y));
        } else if (k == 256) {
            float2 x = fd[256];
            z = make_float2(x.x, -x.y);
        } else if (k < 256) {
            float2 Xk = fd[k], Xk2 = fd[512 - k];
            float ex = 0.5f * (Xk.x + Xk2.x), ey = 0.5f * (Xk.y - Xk2.y);
            float dx = Xk.x - Xk2.x, dy = Xk.y + Xk2.y;
            float2 w = g_w1024[k];
            float ox = 0.5f * (dx * w.x + dy * w.y);
            float oy = 0.5f * (dy * w.x - dx * w.y);
            z = make_float2(ex - oy, ey + ox);
        } else {
            int kk = 512 - k;
            float2 Xk = fd[kk], Xk2 = fd[k];
            float ex = 0.5f * (Xk.x + Xk2.x), ey = 0.5f * (Xk.y - Xk2.y);
            float dx = Xk.x - Xk2.x, dy = Xk.y + Xk2.y;
            float2 w = g_w1024[kk];
            float ox = 0.5f * (dx * w.x + dy * w.y);
            float oy = 0.5f * (dy * w.x - dx * w.y);
            z = make_float2(ex + oy, ox - ey);
        }
        a[q] = z;
    }
    fft512_reg<true>(a, sb, t);

    const float sc = 1.f / 512.f;
    int4* td4 = (int4*)(g_tdb + node * PD);
    float2* s = sb;
#pragma unroll
    for (int h = 0; h < 2; h++) {
        union { int4 v; __nv_bfloat162 e[4]; } u;
#pragma unroll
        for (int e2 = 0; e2 < 4; e2++) {
            float2 z = s[9 * t + h * 4 + e2];
            u.e[e2] = __floats2bfloat162_rn(z.x * sc, z.y * sc);
        }
        td4[2 * t + h] = u.v;
    }
}

// ===========================================================================
// bf16 wmma GEMM (R11 proven config): 128x128x32 tile, 8 warps (4x2) of
// 32x64, 3-stage cp.async ring, 60KB dynamic smem, 2 CTAs/SM.
// ===========================================================================
#define BKG 32
#define LDKB 40
#define STG_ELEMS (128 * LDKB)

#define CP_ASYNC16(dst, src) \
    asm volatile("cp.async.cg.shared.global [%0], [%1], 16;\n" :: "r"(dst), "l"(src))
#define CP_COMMIT() asm volatile("cp.async.commit_group;\n" ::: "memory")
#define CP_WAIT(n)  asm volatile("cp.async.wait_group %0;\n" :: "n"(n) : "memory")

__device__ __forceinline__ uint32_t smem_u32(const void* p) {
    uint32_t a;
    asm("{ .reg .u64 t; cvta.to.shared.u64 t, %1; cvt.u32.u64 %0, t; }" : "=r"(a) : "l"(p));
    return a;
}

__global__ __launch_bounds__(256, 2)
void gemm_wmma_kernel(const float* __restrict__ bias,
                      float* __restrict__ out) {
    extern __shared__ __align__(16) char dsm[];
    __nv_bfloat16* As = (__nv_bfloat16*)dsm;
    __nv_bfloat16* Bs = As + 3 * STG_ELEMS;

    const int tid = threadIdx.x;
    const int wid = tid >> 5;
    const int lid = tid & 31;
    const int wr = wid & 3;
    const int wc = wid >> 2;
    const int m0 = blockIdx.y * 128;
    const int c0 = blockIdx.x * 128;
    const __nv_bfloat16* A = g_tdb;

    if (c0 + 128 > PC) {
        for (int st = 0; st < 3; st++)
            for (int idx = tid; idx < STG_ELEMS; idx += 256) {
                int row = idx / LDKB;
                if (c0 + row >= PC) Bs[st * STG_ELEMS + idx] = __float2bfloat16(0.f);
            }
    }
    __syncthreads();

    const uint32_t sAb = smem_u32(As);
    const uint32_t sBb = smem_u32(Bs);

    auto load_stage = [&](int stage, int kk) {
        uint32_t sA = sAb + (uint32_t)stage * STG_ELEMS * 2;
        uint32_t sB = sBb + (uint32_t)stage * STG_ELEMS * 2;
#pragma unroll
        for (int i = 0; i < 2; i++) {
            int idx = tid + i * 256;
            int row = idx >> 2, q = idx & 3;
            CP_ASYNC16(sA + (uint32_t)(row * LDKB + q * 8) * 2,
                       A + (size_t)(m0 + row) * PD + kk + q * 8);
        }
#pragma unroll
        for (int i = 0; i < 2; i++) {
            int idx = tid + i * 256;
            int row = idx >> 2, q = idx & 3;
            if (c0 + row < PC)
                CP_ASYNC16(sB + (uint32_t)(row * LDKB + q * 8) * 2,
                           g_wb + (size_t)(c0 + row) * PD + kk + q * 8);
        }
    };

    wmma::fragment<wmma::accumulator, 16, 16, 16, float> acc[2][4];
#pragma unroll
    for (int i = 0; i < 2; i++)
#pragma unroll
        for (int j = 0; j < 4; j++) wmma::fill_fragment(acc[i][j], 0.f);

    load_stage(0, 0);
    CP_COMMIT();
    load_stage(1, BKG);
    CP_COMMIT();

    const int NK = PD / BKG;
    for (int kt = 0; kt < NK; kt++) {
        if (kt + 1 < NK) { CP_WAIT(1); } else { CP_WAIT(0); }
        __syncthreads();
        if (kt + 2 < NK) {
            load_stage((kt + 2) % 3, (kt + 2) * BKG);
            CP_COMMIT();
        }
        const __nv_bfloat16* Ac = As + (kt % 3) * STG_ELEMS;
        const __nv_bfloat16* Bc = Bs + (kt % 3) * STG_ELEMS;
#pragma unroll
        for (int ks = 0; ks < 2; ks++) {
            wmma::fragment<wmma::matrix_a, 16, 16, 16, __nv_bfloat16, wmma::row_major> af[2];
            wmma::fragment<wmma::matrix_b, 16, 16, 16, __nv_bfloat16, wmma::col_major> bf[4];
#pragma unroll
            for (int i = 0; i < 2; i++)
                wmma::load_matrix_sync(af[i], Ac + (wr * 32 + i * 16) * LDKB + ks * 16, LDKB);
#pragma unroll
            for (int j = 0; j < 4; j++)
                wmma::load_matrix_sync(bf[j], Bc + (wc * 64 + j * 16) * LDKB + ks * 16, LDKB);
#pragma unroll
            for (int i = 0; i < 2; i++)
#pragma unroll
                for (int j = 0; j < 4; j++)
                    wmma::mma_sync(acc[i][j], af[i], bf[j], acc[i][j]);
        }
    }
    __syncthreads();

    // Epilogue: per warp stage a full 16x64 half (4 fragments, stride 68),
    // then 256B-contiguous float4 stores with bias + sigmoid.
    float* stage = (float*)dsm + wid * 1088;
    const int r = lid >> 1;
    const int hcol = (lid & 1) * 32;
#pragma unroll
    for (int i = 0; i < 2; i++) {
#pragma unroll
        for (int j = 0; j < 4; j++)
            wmma::store_matrix_sync(stage + j * 16, acc[i][j], 68, wmma::mem_row_major);
        __syncwarp();
        int m = m0 + wr * 32 + i * 16 + r;
        int cbase = c0 + wc * 64 + hcol;
        float* orow = out + (size_t)m * PC;
        const float* srow = stage + r * 68 + hcol;
#pragma unroll
        for (int k = 0; k < 8; k++) {
            int c = cbase + 4 * k;
            if (c < PC) {
                float4 v = *(const float4*)(srow + 4 * k);
                float4 bb = *(const float4*)(bias + c);
                float4 o;
                o.x = 1.f / (1.f + __expf(-(v.x + bb.x)));
                o.y = 1.f / (1.f + __expf(-(v.y + bb.y)));
                o.z = 1.f / (1.f + __expf(-(v.z + bb.z)));
                o.w = 1.f / (1.f + __expf(-(v.w + bb.w)));
                *(float4*)(orow + c) = o;
            }
        }
        __syncwarp();
    }
}

#define GEMM_SMEM (6 * STG_ELEMS * 2)   // 61440 bytes

// ---------------------------------------------------------------------------
extern "C" void kernel_launch(void* const* d_in, const int* in_sizes, int n_in,
                              void* d_out, int out_size) {
    const int*   ids  = (const int*)d_in[0];
    const int*   mask = (const int*)d_in[1];
    const int*   info = (const int*)d_in[2];
    const float* emb  = (const float*)d_in[3];
    const float* W    = (const float*)d_in[4];
    const float* bias = (const float*)d_in[5];
    float* out = (float*)d_out;

    setup_kernel<<<2 + PC, 256>>>(W);
    leaf_kernel<<<PB * PL, 64>>>(ids, mask, emb);
    compose_kernel<<<PB, 512>>>(info);
    irfft_kernel<<<PB * PS, 64>>>();

    cudaFuncSetAttribute(gemm_wmma_kernel,
                         cudaFuncAttributeMaxDynamicSharedMemorySize, GEMM_SMEM);
    dim3 gg((PC + 127) / 128, (PB * PN) / 128);   // 4 x 254
    gemm_wmma_kernel<<<gg, 256, GEMM_SMEM>>>(bias, out);
}

// round 16
// speedup vs baseline: 1.0443x; 1.0172x over previous
#include <cuda_runtime.h>
#include <cuda_bf16.h>
#include <mma.h>
#include <math.h>
#include <cstdint>

using namespace nvcuda;

// Problem constants
#define PB 256      // batch
#define PL 64       // leaves
#define PD 1024     // dim
#define PC 500      // classes
#define PN 127      // nodes = 2L-1
#define PS 63       // steps = L-1
#define HB 512      // half-spectrum bins stored per node

// Scratch
static __device__ __nv_bfloat16 g_tdb[(size_t)PB * PN * PD];  // 66 MB (GEMM A)
static __device__ float2        g_fd[(size_t)PB * PN * HB];   // 133 MB (half spectra)
static __device__ __nv_bfloat16 g_wb[(size_t)PC * PD];        // 1 MB  (W in bf16)
static __device__ float2        g_w1024[512];                 // W1024^k (untangle)
static __device__ float2        g_w512[512];                  // W512^j  (FFT twiddles)

// ---------------------------------------------------------------------------
// Setup: twiddle tables + W bf16 conversion.
__global__ void setup_kernel(const float* __restrict__ W) {
    int g = blockIdx.x;
    if (g == 0) {
        for (int i = threadIdx.x; i < 512; i += 256) {
            float sn, cs;
            sincosf(-6.283185307179586f * (float)i / 1024.f, &sn, &cs);
            g_w1024[i] = make_float2(cs, sn);
        }
    } else if (g == 1) {
        for (int i = threadIdx.x; i < 512; i += 256) {
            float sn, cs;
            sincosf(-6.283185307179586f * (float)i / 512.f, &sn, &cs);
            g_w512[i] = make_float2(cs, sn);
        }
    } else {
        int i = (g - 2) * 1024 + threadIdx.x * 4;
        float4 v = *(const float4*)(W + i);
        __nv_bfloat16* o = g_wb + i;
        o[0] = __float2bfloat16(v.x);
        o[1] = __float2bfloat16(v.y);
        o[2] = __float2bfloat16(v.z);
        o[3] = __float2bfloat16(v.w);
    }
}

// ---------------------------------------------------------------------------
// Complex helpers
__device__ __forceinline__ float2 cadd(float2 a, float2 b) { return make_float2(a.x + b.x, a.y + b.y); }
__device__ __forceinline__ float2 csub(float2 a, float2 b) { return make_float2(a.x - b.x, a.y - b.y); }
__device__ __forceinline__ float2 cmul(float2 a, float2 b) {
    return make_float2(fmaf(a.x, b.x, -a.y * b.y), fmaf(a.x, b.y, a.y * b.x));
}
template<bool INV>
__device__ __forceinline__ float2 crot(float2 a) {   // * (-i) fwd, * (+i) inv
    return INV ? make_float2(-a.y, a.x) : make_float2(a.y, -a.x);
}

// In-register 8-point DFT, natural-order in/out.
template<bool INV>
__device__ __forceinline__ void fft8(float2* a) {
    const float r = 0.70710678118654752440f;
    const float2 w1 = INV ? make_float2(r, r)  : make_float2(r, -r);
    const float2 w3 = INV ? make_float2(-r, r) : make_float2(-r, -r);
    float2 b0 = cadd(a[0], a[4]), b4 = csub(a[0], a[4]);
    float2 b1 = cadd(a[1], a[5]), b5 = cmul(csub(a[1], a[5]), w1);
    float2 b2 = cadd(a[2], a[6]), b6 = crot<INV>(csub(a[2], a[6]));
    float2 b3 = cadd(a[3], a[7]), b7 = cmul(csub(a[3], a[7]), w3);
    float2 c0 = cadd(b0, b2), c2 = csub(b0, b2);
    float2 c1 = cadd(b1, b3), c3 = crot<INV>(csub(b1, b3));
    float2 c4 = cadd(b4, b6), c6 = csub(b4, b6);
    float2 c5 = cadd(b5, b7), c7 = crot<INV>(csub(b5, b7));
    a[0] = cadd(c0, c1); a[4] = csub(c0, c1);
    a[2] = cadd(c2, c3); a[6] = csub(c2, c3);
    a[1] = cadd(c4, c5); a[5] = csub(c4, c5);
    a[3] = cadd(c6, c7); a[7] = csub(c6, c7);
}

// Padded natural-order index: p(n) = n + n/8 (row stride 9, max 574 < 576).
#define SBP(s, n) ((s)[(n) + ((n) >> 3)])

// 512-pt complex FFT core, radix-8^3, 64 threads (one block), 8 values in
// registers. Ends with the THIRD fft8 done and results in a[j2] for output
// index n = k1 + 8*j1 + 64*j2 (k1 = t>>3, j1 = t&7). No trailing smem store.
template<bool INV>
__device__ __forceinline__ void fft512_core(float2* a, float2* sb, int t) {
    fft8<INV>(a);
    sb[t] = a[0];
#pragma unroll
    for (int k1 = 1; k1 < 8; k1++) {
        float2 w = g_w512[t * k1];
        if (INV) w.y = -w.y;
        sb[72 * k1 + t] = cmul(a[k1], w);
    }
    __syncthreads();
    const int k1 = t >> 3, m2 = t & 7;
    {
        const float2* base = sb + 72 * k1 + m2;
#pragma unroll
        for (int m1 = 0; m1 < 8; m1++) a[m1] = base[8 * m1];
    }
    __syncthreads();
    fft8<INV>(a);
    sb[72 * k1 + m2] = a[0];
#pragma unroll
    for (int j1 = 1; j1 < 8; j1++) {
        float2 w = g_w512[8 * m2 * j1];
        if (INV) w.y = -w.y;
        sb[72 * k1 + 9 * j1 + m2] = cmul(a[j1], w);
    }
    __syncthreads();
    const int j1 = t & 7;
    {
        const float2* base = sb + 72 * k1 + 9 * j1;
#pragma unroll
        for (int m = 0; m < 8; m++) a[m] = base[m];
    }
    __syncthreads();
    fft8<INV>(a);
}

// ---------------------------------------------------------------------------
// Kernel 1: leaf gather + mask + L2-normalize -> bf16 TD; rfft -> half FD.
// One leaf per 64-thread block.
__global__ __launch_bounds__(64) void leaf_kernel(const int* __restrict__ ids,
                                                  const int* __restrict__ mask,
                                                  const float* __restrict__ emb) {
    __shared__ float2 sb[576];
    __shared__ float red[2];
    int t = threadIdx.x;
    int blk = blockIdx.x;                           // global leaf index b*64+l
    int id = __ldg(ids + blk);
    int mk = __ldg(mask + blk);
    const float2* row = (const float2*)emb + (size_t)id * (PD / 2);

    float2 a[8];
    float ss = 0.f;
#pragma unroll
    for (int q = 0; q < 8; q++) {
        float2 v = row[t + 64 * q];
        if (mk <= 0) v = make_float2(0.f, 0.f);
        a[q] = v;
        ss += v.x * v.x + v.y * v.y;
    }
#pragma unroll
    for (int o = 16; o > 0; o >>= 1) ss += __shfl_xor_sync(0xffffffffu, ss, o);
    if ((t & 31) == 0) red[t >> 5] = ss;
    __syncthreads();
    ss = red[0] + red[1];
    float inv = 1.f / (sqrtf(ss) + 1e-6f);

    int b = blk >> 6, l = blk & 63;
    size_t node = (size_t)b * PN + l;
    __nv_bfloat162* td2 = (__nv_bfloat162*)(g_tdb + node * PD);
#pragma unroll
    for (int q = 0; q < 8; q++) {
        a[q].x *= inv; a[q].y *= inv;
        td2[t + 64 * q] = __floats2bfloat162_rn(a[q].x, a[q].y);
    }
    fft512_core<false>(a, sb, t);

    // Natural-order padded store (untangle needs k <-> 512-k pairing).
    const int k1 = t >> 3, j1 = t & 7;
#pragma unroll
    for (int j2 = 0; j2 < 8; j2++) {
        int n = k1 + 8 * j1 + 64 * j2;
        SBP(sb, n) = a[j2];
    }
    __syncthreads();

    float2* fd = g_fd + node * HB;
    float2* s = sb;
#pragma unroll
    for (int q = 0; q < 4; q++) {
        int k = t + 64 * q;
        if (k == 0) {
            float2 z0 = SBP(s, 0);
            fd[0] = make_float2(z0.x + z0.y, z0.x - z0.y);
            float2 z = SBP(s, 256);
            fd[256] = make_float2(z.x, -z.y);
        } else {
            float2 zk = SBP(s, k), zk2 = SBP(s, 512 - k);
            float ex = 0.5f * (zk.x + zk2.x), ey = 0.5f * (zk.y - zk2.y);
            float dx = zk.x - zk2.x, dy = zk.y + zk2.y;
            float ox = 0.5f * dy, oy = -0.5f * dx;
            float2 w = g_w1024[k];
            float wx = w.x * ox - w.y * oy;
            float wy = w.x * oy + w.y * ox;
            fd[k]       = make_float2(ex + wx, ey + wy);
            fd[512 - k] = make_float2(ex - wx, -(ey - wy));
        }
    }
}

// ---------------------------------------------------------------------------
// Kernel 2: per-batch sequential composition on 512 half-spectrum bins.
__global__ void compose_kernel(const int* __restrict__ info) {
    __shared__ float2 sh[HB];
    __shared__ float red[2][16];
    int b = blockIdx.x, tid = threadIdx.x;
    const int lane = tid & 31, wrp = tid >> 5;
    const int* bi = info + (size_t)b * PS * 3;
    float2* fdb = g_fd + (size_t)b * PN * HB;

    int i0 = bi[0], i1 = bi[1], i2 = bi[2];
    float2 pl = fdb[(size_t)i0 * HB + tid];
    float2 pr = fdb[(size_t)i1 * HB + tid];
    int last = -1;
    for (int st = 0; st < PS; st++) {
        float2 fl = (i0 == last) ? sh[tid] : pl;
        float2 fr = (i1 == last) ? sh[tid] : pr;
        float2 c;
        float ss;
        if (tid == 0) {
            c = make_float2(fl.x * fr.x, fl.y * fr.y);
            ss = c.x * c.x + c.y * c.y;
        } else {
            c = make_float2(fl.x * fr.x + fl.y * fr.y,
                            fl.x * fr.y - fl.y * fr.x);
            ss = 2.f * (c.x * c.x + c.y * c.y);
        }
        int n0 = i0, n1 = i1, n2 = i2;
        if (st + 1 < PS) {
            n0 = bi[(st + 1) * 3 + 0];
            n1 = bi[(st + 1) * 3 + 1];
            n2 = bi[(st + 1) * 3 + 2];
            if (n0 != i2) pl = fdb[(size_t)n0 * HB + tid];
            if (n1 != i2) pr = fdb[(size_t)n1 * HB + tid];
        }
        float* rb = red[st & 1];
#pragma unroll
        for (int o = 16; o > 0; o >>= 1) ss += __shfl_xor_sync(0xffffffffu, ss, o);
        if (lane == 0) rb[wrp] = ss;
        __syncthreads();
        float tot = 0.f;
#pragma unroll
        for (int i = 0; i < 16; i++) tot += rb[i];

        float inv = 1.f / (sqrtf(tot * (1.f / (float)PD)) + 1e-6f);
        float2 cc = make_float2(c.x * inv, c.y * inv);
        sh[tid] = cc;
        fdb[(size_t)i2 * HB + tid] = cc;
        last = i2; i0 = n0; i1 = n1; i2 = n2;
    }
}

// ---------------------------------------------------------------------------
// Kernel 3: inverse rfft of internal nodes -> bf16 TD. One node per 64-thread
// block; final stage writes registers DIRECTLY to global (no smem round-trip).
__global__ __launch_bounds__(64) void irfft_kernel() {
    __shared__ float2 sb[576];
    int t = threadIdx.x;
    int blk = blockIdx.x;                           // 0..16127
    int b = blk / PS, s0 = blk - b * PS;
    size_t node = (size_t)b * PN + PL + s0;
    const float2* fd = g_fd + node * HB;

    float2 a[8];
#pragma unroll
    for (int q = 0; q < 8; q++) {
        int k = t + 64 * q;
        float2 z;
        if (k == 0) {
            float2 p = fd[0];
            z = make_float2(0.5f * (p.x + p.y), 0.5f * (p.x - p.y));
        } else if (k == 256) {
            float2 x = fd[256];
            z = make_float2(x.x, -x.y);
        } else if (k < 256) {
            float2 Xk = fd[k], Xk2 = fd[512 - k];
            float ex = 0.5f * (Xk.x + Xk2.x), ey = 0.5f * (Xk.y - Xk2.y);
            float dx = Xk.x - Xk2.x, dy = Xk.y + Xk2.y;
            float2 w = g_w1024[k];
            float ox = 0.5f * (dx * w.x + dy * w.y);
            float oy = 0.5f * (dy * w.x - dx * w.y);
            z = make_float2(ex - oy, ey + ox);
        } else {
            int kk = 512 - k;
            float2 Xk = fd[kk], Xk2 = fd[k];
            float ex = 0.5f * (Xk.x + Xk2.x), ey = 0.5f * (Xk.y - Xk2.y);
            float dx = Xk.x - Xk2.x, dy = Xk.y + Xk2.y;
            float2 w = g_w1024[kk];
            float ox = 0.5f * (dx * w.x + dy * w.y);
            float oy = 0.5f * (dy * w.x - dx * w.y);
            z = make_float2(ex + oy, ox - ey);
        }
        a[q] = z;
    }
    fft512_core<true>(a, sb, t);

    // Direct writeout: a[j2] is z[n], n = k1 + 8*j1 + 64*j2. Each j2-slice's
    // 64 stores (4B) cover one 256B window -> full sector utilization.
    const float sc = 1.f / 512.f;
    const int base = (t >> 3) + 8 * (t & 7);
    __nv_bfloat162* td2 = (__nv_bfloat162*)(g_tdb + node * PD);
#pragma unroll
    for (int j2 = 0; j2 < 8; j2++)
        td2[base + 64 * j2] = __floats2bfloat162_rn(a[j2].x * sc, a[j2].y * sc);
}

// ===========================================================================
// bf16 wmma GEMM (R11 proven config): 128x128x32 tile, 8 warps (4x2) of
// 32x64, 3-stage cp.async ring, 60KB dynamic smem, 2 CTAs/SM.
// ===========================================================================
#define BKG 32
#define LDKB 40
#define STG_ELEMS (128 * LDKB)

#define CP_ASYNC16(dst, src) \
    asm volatile("cp.async.cg.shared.global [%0], [%1], 16;\n" :: "r"(dst), "l"(src))
#define CP_COMMIT() asm volatile("cp.async.commit_group;\n" ::: "memory")
#define CP_WAIT(n)  asm volatile("cp.async.wait_group %0;\n" :: "n"(n) : "memory")

__device__ __forceinline__ uint32_t smem_u32(const void* p) {
    uint32_t a;
    asm("{ .reg .u64 t; cvta.to.shared.u64 t, %1; cvt.u32.u64 %0, t; }" : "=r"(a) : "l"(p));
    return a;
}

__global__ __launch_bounds__(256, 2)
void gemm_wmma_kernel(const float* __restrict__ bias,
                      float* __restrict__ out) {
    extern __shared__ __align__(16) char dsm[];
    __nv_bfloat16* As = (__nv_bfloat16*)dsm;
    __nv_bfloat16* Bs = As + 3 * STG_ELEMS;

    const int tid = threadIdx.x;
    const int wid = tid >> 5;
    const int lid = tid & 31;
    const int wr = wid & 3;
    const int wc = wid >> 2;
    const int m0 = blockIdx.y * 128;
    const int c0 = blockIdx.x * 128;
    const __nv_bfloat16* A = g_tdb;

    if (c0 + 128 > PC) {
        for (int st = 0; st < 3; st++)
            for (int idx = tid; idx < STG_ELEMS; idx += 256) {
                int row = idx / LDKB;
                if (c0 + row >= PC) Bs[st * STG_ELEMS + idx] = __float2bfloat16(0.f);
            }
    }
    __syncthreads();

    const uint32_t sAb = smem_u32(As);
    const uint32_t sBb = smem_u32(Bs);

    auto load_stage = [&](int stage, int kk) {
        uint32_t sA = sAb + (uint32_t)stage * STG_ELEMS * 2;
        uint32_t sB = sBb + (uint32_t)stage * STG_ELEMS * 2;
#pragma unroll
        for (int i = 0; i < 2; i++) {
            int idx = tid + i * 256;
            int row = idx >> 2, q = idx & 3;
            CP_ASYNC16(sA + (uint32_t)(row * LDKB + q * 8) * 2,
                       A + (size_t)(m0 + row) * PD + kk + q * 8);
        }
#pragma unroll
        for (int i = 0; i < 2; i++) {
            int idx = tid + i * 256;
            int row = idx >> 2, q = idx & 3;
            if (c0 + row < PC)
                CP_ASYNC16(sB + (uint32_t)(row * LDKB + q * 8) * 2,
                           g_wb + (size_t)(c0 + row) * PD + kk + q * 8);
        }
    };

    wmma::fragment<wmma::accumulator, 16, 16, 16, float> acc[2][4];
#pragma unroll
    for (int i = 0; i < 2; i++)
#pragma unroll
        for (int j = 0; j < 4; j++) wmma::fill_fragment(acc[i][j], 0.f);

    load_stage(0, 0);
    CP_COMMIT();
    load_stage(1, BKG);
    CP_COMMIT();

    const int NK = PD / BKG;
    for (int kt = 0; kt < NK; kt++) {
        if (kt + 1 < NK) { CP_WAIT(1); } else { CP_WAIT(0); }
        __syncthreads();
        if (kt + 2 < NK) {
            load_stage((kt + 2) % 3, (kt + 2) * BKG);
            CP_COMMIT();
        }
        const __nv_bfloat16* Ac = As + (kt % 3) * STG_ELEMS;
        const __nv_bfloat16* Bc = Bs + (kt % 3) * STG_ELEMS;
#pragma unroll
        for (int ks = 0; ks < 2; ks++) {
            wmma::fragment<wmma::matrix_a, 16, 16, 16, __nv_bfloat16, wmma::row_major> af[2];
            wmma::fragment<wmma::matrix_b, 16, 16, 16, __nv_bfloat16, wmma::col_major> bf[4];
#pragma unroll
            for (int i = 0; i < 2; i++)
                wmma::load_matrix_sync(af[i], Ac + (wr * 32 + i * 16) * LDKB + ks * 16, LDKB);
#pragma unroll
            for (int j = 0; j < 4; j++)
                wmma::load_matrix_sync(bf[j], Bc + (wc * 64 + j * 16) * LDKB + ks * 16, LDKB);
#pragma unroll
            for (int i = 0; i < 2; i++)
#pragma unroll
                for (int j = 0; j < 4; j++)
                    wmma::mma_sync(acc[i][j], af[i], bf[j], acc[i][j]);
        }
    }
    __syncthreads();

    // Epilogue: per warp stage a full 16x64 half (4 fragments, stride 68),
    // then 256B-contiguous float4 stores with bias + sigmoid.
    float* stage = (float*)dsm + wid * 1088;
    const int r = lid >> 1;
    const int hcol = (lid & 1) * 32;
#pragma unroll
    for (int i = 0; i < 2; i++) {
#pragma unroll
        for (int j = 0; j < 4; j++)
            wmma::store_matrix_sync(stage + j * 16, acc[i][j], 68, wmma::mem_row_major);
        __syncwarp();
        int m = m0 + wr * 32 + i * 16 + r;
        int cbase = c0 + wc * 64 + hcol;
        float* orow = out + (size_t)m * PC;
        const float* srow = stage + r * 68 + hcol;
#pragma unroll
        for (int k = 0; k < 8; k++) {
            int c = cbase + 4 * k;
            if (c < PC) {
                float4 v = *(const float4*)(srow + 4 * k);
                float4 bb = *(const float4*)(bias + c);
                float4 o;
                o.x = 1.f / (1.f + __expf(-(v.x + bb.x)));
                o.y = 1.f / (1.f + __expf(-(v.y + bb.y)));
                o.z = 1.f / (1.f + __expf(-(v.z + bb.z)));
                o.w = 1.f / (1.f + __expf(-(v.w + bb.w)));
                *(float4*)(orow + c) = o;
            }
        }
        __syncwarp();
    }
}

#define GEMM_SMEM (6 * STG_ELEMS * 2)   // 61440 bytes

// ---------------------------------------------------------------------------
extern "C" void kernel_launch(void* const* d_in, const int* in_sizes, int n_in,
                              void* d_out, int out_size) {
    const int*   ids  = (const int*)d_in[0];
    const int*   mask = (const int*)d_in[1];
    const int*   info = (const int*)d_in[2];
    const float* emb  = (const float*)d_in[3];
    const float* W    = (const float*)d_in[4];
    const float* bias = (const float*)d_in[5];
    float* out = (float*)d_out;

    setup_kernel<<<2 + PC, 256>>>(W);
    leaf_kernel<<<PB * PL, 64>>>(ids, mask, emb);
    compose_kernel<<<PB, 512>>>(info);
    irfft_kernel<<<PB * PS, 64>>>();

    cudaFuncSetAttribute(gemm_wmma_kernel,
                         cudaFuncAttributeMaxDynamicSharedMemorySize, GEMM_SMEM);
    dim3 gg((PC + 127) / 128, (PB * PN) / 128);   // 4 x 254
    gemm_wmma_kernel<<<gg, 256, GEMM_SMEM>>>(bias, out);
}